// round 14
// baseline (speedup 1.0000x reference)
#include <cuda_runtime.h>
#include <cuda_bf16.h>
#include <cstdint>

#define K1    4096
#define K3    8192           // stored K: [hi | lo] segments
#define N_DIM 2048
#define M_DIM 8192
#define DGRP  8
#define KCB   256

// GEMM: 128x128 CTA, 256 threads (8 warps, 4x2 grid of 32x64 warp tiles)
// split-K = 2 via blockIdx.z (each CTA does K1/2 = 2048 cols => 32 stages/phase)
#define BM2    128
#define BN2    128
#define A_TILE 16384                       // 128 rows x 128B
#define PH_A_STAGE (3 * A_TILE)            // xh + xl + wh = 49152
#define PH_B_STAGE (2 * A_TILE)            // xh + wl      = 32768
#define SMEM_G 98304                       // 2 x phaseA == 3 x phaseB ; 2 CTAs/SM
#define NSTG   32                          // stages per phase per K-split

// fused prep grid: 2048 quantize rows + 32768 convert chunks, interleaved 1:16
#define QR 17
#define PREP_GRID (2048 + 32768)

__device__ __align__(256) __nv_bfloat16 g_xcat[(size_t)M_DIM * K3];  // [xhi|xlo]
__device__ __align__(256) __nv_bfloat16 g_wcat[(size_t)N_DIM * K3];  // [whi|wlo]
__device__ __align__(256) float         g_part[(size_t)M_DIM * N_DIM]; // split-1 partials

// ---------------- PTX helpers ----------------
__device__ __forceinline__ uint32_t smem_u32(const void* p) {
    uint32_t a;
    asm("{ .reg .u64 t; cvta.to.shared.u64 t, %1; cvt.u32.u64 %0, t; }" : "=r"(a) : "l"(p));
    return a;
}
#define CP_ASYNC16(dst, src) \
    asm volatile("cp.async.cg.shared.global [%0], [%1], 16;" :: "r"(dst), "l"(src))
#define CP_COMMIT() asm volatile("cp.async.commit_group;" ::: "memory")
#define CP_WAIT1()  asm volatile("cp.async.wait_group 1;" ::: "memory")
#define CP_WAIT0()  asm volatile("cp.async.wait_group 0;" ::: "memory")

#define LDSM_X4(r0,r1,r2,r3,addr) \
    asm volatile("ldmatrix.sync.aligned.m8n8.x4.shared.b16 {%0,%1,%2,%3}, [%4];" \
                 : "=r"(r0), "=r"(r1), "=r"(r2), "=r"(r3) : "r"(addr))

#define MMA16816(d, a0,a1,a2,a3, b0,b1) \
    asm volatile("mma.sync.aligned.m16n8k16.row.col.f32.bf16.bf16.f32 " \
                 "{%0,%1,%2,%3},{%4,%5,%6,%7},{%8,%9},{%0,%1,%2,%3};" \
                 : "+f"((d)[0]), "+f"((d)[1]), "+f"((d)[2]), "+f"((d)[3]) \
                 : "r"(a0), "r"(a1), "r"(a2), "r"(a3), "r"(b0), "r"(b1))

// ---------------- Kernel 1 (fused): quantize rows || x bf16 hi/lo convert ----------------
__global__ __launch_bounds__(256)
void pq_prep(const float* __restrict__ weight, const float* __restrict__ codebook,
             const float* __restrict__ x) {
    const int bid = blockIdx.x;
    const int tid = threadIdx.x;

    if (bid % QR != 0) {
        // ---- convert branch: one float4 of x per thread ----
        size_t conv_idx = (size_t)bid - bid / QR - 1;     // 0..32767
        size_t idx = conv_idx * 256 + tid;
        float4 v = ((const float4*)x)[idx];
        size_t m = idx >> 10;
        size_t kq = (idx & 1023) << 2;

        __nv_bfloat16 h0 = __float2bfloat16(v.x), h1 = __float2bfloat16(v.y);
        __nv_bfloat16 h2 = __float2bfloat16(v.z), h3 = __float2bfloat16(v.w);
        __nv_bfloat16 l0 = __float2bfloat16(v.x - __bfloat162float(h0));
        __nv_bfloat16 l1 = __float2bfloat16(v.y - __bfloat162float(h1));
        __nv_bfloat16 l2 = __float2bfloat16(v.z - __bfloat162float(h2));
        __nv_bfloat16 l3 = __float2bfloat16(v.w - __bfloat162float(h3));

        union { __nv_bfloat16 b[4]; uint2 u; } ph, pl;
        ph.b[0]=h0; ph.b[1]=h1; ph.b[2]=h2; ph.b[3]=h3;
        pl.b[0]=l0; pl.b[1]=l1; pl.b[2]=l2; pl.b[3]=l3;

        size_t base = m * K3 + kq;
        *(uint2*)(g_xcat + base)      = ph.u;   // x_hi
        *(uint2*)(g_xcat + base + K1) = pl.u;   // x_lo
        return;
    }

    // ---- quantize branch: one weight row ----
    __shared__ float cb[KCB * DGRP];
    __shared__ float cnorm_half[KCB];
    __shared__ float red[256];

    const int o = bid / QR;

    for (int i = tid; i < KCB * DGRP; i += 256) cb[i] = codebook[i];
    __syncthreads();
    {
        float s = 0.f;
        #pragma unroll
        for (int j = 0; j < DGRP; j++) { float c = cb[tid * DGRP + j]; s = fmaf(c, c, s); }
        cnorm_half[tid] = 0.5f * s;
    }
    const float* wrow = weight + (size_t)o * K1;
    float m = 0.f;
    for (int i = tid; i < K1; i += 256) m = fmaxf(m, fabsf(wrow[i]));
    red[tid] = m;
    __syncthreads();
    for (int s = 128; s > 0; s >>= 1) { if (tid < s) red[tid] = fmaxf(red[tid], red[tid + s]); __syncthreads(); }
    const float scale = fmaxf(red[0], 1e-6f);
    const float inv = 1.f / scale;

    const float4* wrow4 = (const float4*)wrow;
    float4 ga0 = wrow4[tid * 2],         ga1 = wrow4[tid * 2 + 1];
    float4 gb0 = wrow4[(tid + 256) * 2], gb1 = wrow4[(tid + 256) * 2 + 1];
    float gva[DGRP] = {ga0.x*inv, ga0.y*inv, ga0.z*inv, ga0.w*inv,
                       ga1.x*inv, ga1.y*inv, ga1.z*inv, ga1.w*inv};
    float gvb[DGRP] = {gb0.x*inv, gb0.y*inv, gb0.z*inv, gb0.w*inv,
                       gb1.x*inv, gb1.y*inv, gb1.z*inv, gb1.w*inv};

    float best0 = 3.4e38f, best1 = 3.4e38f;
    int bi0 = 0, bi1 = 0;
    const float4* cb4 = (const float4*)cb;
    #pragma unroll 2
    for (int k = 0; k < KCB; k++) {
        float4 c0 = cb4[k * 2], c1 = cb4[k * 2 + 1];
        float cn = cnorm_half[k];
        float d0 = cn, d1 = cn;
        d0 = fmaf(-gva[0], c0.x, d0); d1 = fmaf(-gvb[0], c0.x, d1);
        d0 = fmaf(-gva[1], c0.y, d0); d1 = fmaf(-gvb[1], c0.y, d1);
        d0 = fmaf(-gva[2], c0.z, d0); d1 = fmaf(-gvb[2], c0.z, d1);
        d0 = fmaf(-gva[3], c0.w, d0); d1 = fmaf(-gvb[3], c0.w, d1);
        d0 = fmaf(-gva[4], c1.x, d0); d1 = fmaf(-gvb[4], c1.x, d1);
        d0 = fmaf(-gva[5], c1.y, d0); d1 = fmaf(-gvb[5], c1.y, d1);
        d0 = fmaf(-gva[6], c1.z, d0); d1 = fmaf(-gvb[6], c1.z, d1);
        d0 = fmaf(-gva[7], c1.w, d0); d1 = fmaf(-gvb[7], c1.w, d1);
        if (d0 < best0) { best0 = d0; bi0 = k; }   // strict < keeps first min (matches argmin)
        if (d1 < best1) { best1 = d1; bi1 = k; }
    }

    __nv_bfloat16* wr = g_wcat + (size_t)o * K3;
    #pragma unroll
    for (int j = 0; j < DGRP; j++) {
        float w = cb[bi0 * DGRP + j] * scale;
        __nv_bfloat16 hi = __float2bfloat16(w);
        __nv_bfloat16 lo = __float2bfloat16(w - __bfloat162float(hi));
        int i = tid * DGRP + j;
        wr[i] = hi; wr[K1 + i] = lo;
    }
    #pragma unroll
    for (int j = 0; j < DGRP; j++) {
        float w = cb[bi1 * DGRP + j] * scale;
        __nv_bfloat16 hi = __float2bfloat16(w);
        __nv_bfloat16 lo = __float2bfloat16(w - __bfloat162float(hi));
        int i = (tid + 256) * DGRP + j;
        wr[i] = hi; wr[K1 + i] = lo;
    }
}

// ---------------- Kernel 2: bf16 HMMA GEMM, two-phase, 128x128, split-K=2 ----------------
// blockIdx.z selects K-half (2048 cols = 32 stages per phase).
// z=0 -> raw partial into out ; z=1 -> raw partial into g_part. Bias added in reduce.
__global__ __launch_bounds__(256, 2)
void pq_gemm_mma(float* __restrict__ out) {
    extern __shared__ char smem[];
    const uint32_t sbase = smem_u32(smem);
    const int tid  = threadIdx.x;
    const int wid  = tid >> 5;
    const int lane = tid & 31;

    const size_t m0 = (size_t)blockIdx.y * BM2;
    const size_t n0 = (size_t)blockIdx.x * BN2;
    const size_t gstride = (size_t)K3 * 2;        // row bytes
    const size_t kbase = (size_t)blockIdx.z * 4096;  // byte offset into each segment

    const char* ga[4]; const char* gb[4]; uint32_t chA[4], chB[4];
    #pragma unroll
    for (int i = 0; i < 4; i++) {
        int c = tid + 256 * i, row = c >> 3, ci = c & 7;
        uint32_t off = (uint32_t)(row * 128 + ((ci * 16) ^ ((row & 7) << 4)));
        ga[i] = (const char*)g_xcat + (m0 + row) * gstride + ci * 16 + kbase;
        gb[i] = (const char*)g_wcat + (n0 + row) * gstride + ci * 16 + kbase;
        chA[i] = off; chB[i] = off;
    }

    const int warp_m = (wid & 3) * 32;
    const int warp_n = (wid >> 2) * 64;
    const int rA  = warp_m + (lane & 7) + ((lane >> 3) & 1) * 8;
    const int ksA = ((lane >> 4) & 1) * 16;
    const int xmA = (rA & 7) << 4;
    const int rB  = warp_n + (lane & 7) + ((lane >> 4) & 1) * 8;
    const int ksB = ((lane >> 3) & 1) * 16;
    const int xmB = (rB & 7) << 4;

    float acc[2][8][4];
    #pragma unroll
    for (int i = 0; i < 2; i++)
        #pragma unroll
        for (int j = 0; j < 8; j++)
            #pragma unroll
            for (int q = 0; q < 4; q++) acc[i][j][q] = 0.f;

    // ================= Phase A: 2-stage ring, 48KB stages, 1 barrier/stage =================
    {
        uint32_t bofs = sbase;
        #pragma unroll
        for (int i = 0; i < 4; i++) {
            CP_ASYNC16(bofs + chA[i],            ga[i]);           // xh
            CP_ASYNC16(bofs + A_TILE + chA[i],   ga[i] + 8192);    // xl
            CP_ASYNC16(bofs + 2*A_TILE + chB[i], gb[i]);           // wh
        }
        CP_COMMIT();
    }

    for (int s = 0; s < NSTG; s++) {
        CP_WAIT0();        // stage s fully landed (only group in flight)
        __syncthreads();   // all warps finished compute(s-1) + see buf s

        if (s + 1 < NSTG) {
            uint32_t bofs = sbase + ((s + 1) & 1) * PH_A_STAGE;
            size_t ko = (size_t)(s + 1) * 128;
            #pragma unroll
            for (int i = 0; i < 4; i++) {
                CP_ASYNC16(bofs + chA[i],            ga[i] + ko);
                CP_ASYNC16(bofs + A_TILE + chA[i],   ga[i] + ko + 8192);
                CP_ASYNC16(bofs + 2*A_TILE + chB[i], gb[i] + ko);
            }
        }
        CP_COMMIT();

        const uint32_t sXH = sbase + (s & 1) * PH_A_STAGE;
        const uint32_t sXL = sXH + A_TILE;
        const uint32_t sWH = sXH + 2 * A_TILE;

        #pragma unroll
        for (int ks = 0; ks < 4; ks++) {
            uint32_t ah[2][4], al[2][4];
            #pragma unroll
            for (int i = 0; i < 2; i++) {
                uint32_t aoff = (rA + i * 16) * 128 + ((ks * 32 + ksA) ^ xmA);
                LDSM_X4(ah[i][0], ah[i][1], ah[i][2], ah[i][3], sXH + aoff);
                LDSM_X4(al[i][0], al[i][1], al[i][2], al[i][3], sXL + aoff);
            }
            uint32_t b[4][4];
            #pragma unroll
            for (int blk = 0; blk < 4; blk++) {
                uint32_t boff = (rB + blk * 16) * 128 + ((ks * 32 + ksB) ^ xmB);
                LDSM_X4(b[blk][0], b[blk][1], b[blk][2], b[blk][3], sWH + boff);
            }
            #pragma unroll
            for (int i = 0; i < 2; i++)
                #pragma unroll
                for (int jj = 0; jj < 8; jj++) {
                    int blk = jj >> 1, hb = (jj & 1) * 2;
                    MMA16816(acc[i][jj], ah[i][0], ah[i][1], ah[i][2], ah[i][3],
                             b[blk][hb], b[blk][hb + 1]);
                    MMA16816(acc[i][jj], al[i][0], al[i][1], al[i][2], al[i][3],
                             b[blk][hb], b[blk][hb + 1]);
                }
        }
    }

    // ================= Phase transition =================
    CP_WAIT0();
    __syncthreads();
    #pragma unroll
    for (int s = 0; s < 2; s++) {
        uint32_t bofs = sbase + s * PH_B_STAGE;
        size_t ko = (size_t)s * 128;
        #pragma unroll
        for (int i = 0; i < 4; i++) {
            CP_ASYNC16(bofs + chA[i],          ga[i] + ko);          // xh
            CP_ASYNC16(bofs + A_TILE + chB[i], gb[i] + ko + 8192);   // wl
        }
        CP_COMMIT();
    }

    // ================= Phase B: 3-stage ring, 1 barrier/stage =================
    for (int s = 0; s < NSTG; s++) {
        CP_WAIT1();
        __syncthreads();   // separates compute(s-1) from prefetch (s+2)%3 == (s-1)%3

        if (s + 2 < NSTG) {
            uint32_t bofs = sbase + ((s + 2) % 3) * PH_B_STAGE;
            size_t ko = (size_t)(s + 2) * 128;
            #pragma unroll
            for (int i = 0; i < 4; i++) {
                CP_ASYNC16(bofs + chA[i],          ga[i] + ko);
                CP_ASYNC16(bofs + A_TILE + chB[i], gb[i] + ko + 8192);
            }
        }
        CP_COMMIT();

        const uint32_t sA = sbase + (s % 3) * PH_B_STAGE;
        const uint32_t sB = sA + A_TILE;

        #pragma unroll
        for (int ks = 0; ks < 4; ks++) {
            uint32_t a[2][4];
            #pragma unroll
            for (int i = 0; i < 2; i++) {
                uint32_t aoff = (rA + i * 16) * 128 + ((ks * 32 + ksA) ^ xmA);
                LDSM_X4(a[i][0], a[i][1], a[i][2], a[i][3], sA + aoff);
            }
            uint32_t b[4][4];
            #pragma unroll
            for (int blk = 0; blk < 4; blk++) {
                uint32_t boff = (rB + blk * 16) * 128 + ((ks * 32 + ksB) ^ xmB);
                LDSM_X4(b[blk][0], b[blk][1], b[blk][2], b[blk][3], sB + boff);
            }
            #pragma unroll
            for (int i = 0; i < 2; i++)
                #pragma unroll
                for (int jj = 0; jj < 8; jj++) {
                    int blk = jj >> 1, hb = (jj & 1) * 2;
                    MMA16816(acc[i][jj], a[i][0], a[i][1], a[i][2], a[i][3],
                             b[blk][hb], b[blk][hb + 1]);
                }
        }
    }

    // epilogue: raw partial stores (no bias; reduce adds it once)
    float* dst = blockIdx.z ? g_part : out;
    const int mrow = (int)m0 + warp_m + (lane >> 2);
    const int ncol = (int)n0 + warp_n + (lane & 3) * 2;
    #pragma unroll
    for (int i = 0; i < 2; i++) {
        #pragma unroll
        for (int jj = 0; jj < 8; jj++) {
            int col = ncol + jj * 8;
            int r0 = mrow + i * 16, r1 = r0 + 8;
            float2 v0, v1;
            v0.x = acc[i][jj][0]; v0.y = acc[i][jj][1];
            v1.x = acc[i][jj][2]; v1.y = acc[i][jj][3];
            *(float2*)(dst + (size_t)r0 * N_DIM + col) = v0;
            *(float2*)(dst + (size_t)r1 * N_DIM + col) = v1;
        }
    }
}

// ---------------- Kernel 3: out = out + g_part + bias ----------------
__global__ __launch_bounds__(256)
void pq_reduce(float* __restrict__ out, const float* __restrict__ bias) {
    size_t idx = (size_t)blockIdx.x * 256 + threadIdx.x;   // one float4
    float4 a = ((const float4*)out)[idx];
    float4 b = ((const float4*)g_part)[idx];
    float4 bv = ((const float4*)bias)[idx & 511];           // (idx*4) % 2048 / 4
    float4 r;
    r.x = a.x + b.x + bv.x;
    r.y = a.y + b.y + bv.y;
    r.z = a.z + b.z + bv.z;
    r.w = a.w + b.w + bv.w;
    ((float4*)out)[idx] = r;
}

// ---------------- launch ----------------
extern "C" void kernel_launch(void* const* d_in, const int* in_sizes, int n_in,
                              void* d_out, int out_size) {
    const float* x        = (const float*)d_in[0];
    const float* weight   = (const float*)d_in[1];
    const float* codebook = (const float*)d_in[2];
    const float* bias     = (const float*)d_in[3];
    float* out = (float*)d_out;

    pq_prep<<<PREP_GRID, 256>>>(weight, codebook, x);

    cudaFuncSetAttribute(pq_gemm_mma, cudaFuncAttributeMaxDynamicSharedMemorySize, SMEM_G);
    dim3 grid(N_DIM / BN2, M_DIM / BM2, 2);   // (16, 64, 2) = 2048 CTAs
    pq_gemm_mma<<<grid, 256, SMEM_G>>>(out);

    pq_reduce<<<(M_DIM * N_DIM / 4) / 256, 256>>>(out, bias);
}

// round 15
// speedup vs baseline: 1.1471x; 1.1471x over previous
#include <cuda_runtime.h>
#include <cuda_bf16.h>
#include <cstdint>

#define K1    4096
#define K3    8192           // stored K: [hi | lo] segments
#define N_DIM 2048
#define M_DIM 8192
#define DGRP  8
#define KCB   256

// GEMM: 128x128 CTA, 256 threads (8 warps, 4x2 grid of 32x64 warp tiles)
// split-K = 2 via blockIdx.z (each CTA does K1/2 = 2048 cols => 32 stages/phase)
#define BM2    128
#define BN2    128
#define A_TILE 16384                       // 128 rows x 128B
#define PH_A_STAGE (3 * A_TILE)            // xh + xl + wh = 49152
#define PH_B_STAGE (2 * A_TILE)            // xh + wl      = 32768
#define SMEM_G 98304                       // 2 x phaseA == 3 x phaseB ; 2 CTAs/SM
#define NSTG   32                          // stages per phase per K-split

// fused prep grid: 2048 quantize rows + 32768 convert chunks, interleaved 1:16
#define QR 17
#define PREP_GRID (2048 + 32768)

__device__ __align__(256) __nv_bfloat16 g_xcat[(size_t)M_DIM * K3];  // [xhi|xlo]
__device__ __align__(256) __nv_bfloat16 g_wcat[(size_t)N_DIM * K3];  // [whi|wlo]
__device__ __align__(256) float         g_part[(size_t)M_DIM * N_DIM]; // split-1 partials

// ---------------- PTX helpers ----------------
__device__ __forceinline__ uint32_t smem_u32(const void* p) {
    uint32_t a;
    asm("{ .reg .u64 t; cvta.to.shared.u64 t, %1; cvt.u32.u64 %0, t; }" : "=r"(a) : "l"(p));
    return a;
}
#define CP_ASYNC16(dst, src) \
    asm volatile("cp.async.cg.shared.global [%0], [%1], 16;" :: "r"(dst), "l"(src))
#define CP_COMMIT() asm volatile("cp.async.commit_group;" ::: "memory")
#define CP_WAIT1()  asm volatile("cp.async.wait_group 1;" ::: "memory")
#define CP_WAIT0()  asm volatile("cp.async.wait_group 0;" ::: "memory")

#define LDSM_X4(r0,r1,r2,r3,addr) \
    asm volatile("ldmatrix.sync.aligned.m8n8.x4.shared.b16 {%0,%1,%2,%3}, [%4];" \
                 : "=r"(r0), "=r"(r1), "=r"(r2), "=r"(r3) : "r"(addr))

#define MMA16816(d, a0,a1,a2,a3, b0,b1) \
    asm volatile("mma.sync.aligned.m16n8k16.row.col.f32.bf16.bf16.f32 " \
                 "{%0,%1,%2,%3},{%4,%5,%6,%7},{%8,%9},{%0,%1,%2,%3};" \
                 : "+f"((d)[0]), "+f"((d)[1]), "+f"((d)[2]), "+f"((d)[3]) \
                 : "r"(a0), "r"(a1), "r"(a2), "r"(a3), "r"(b0), "r"(b1))

// ---------------- Kernel 1 (fused): quantize rows || x bf16 hi/lo convert ----------------
__global__ __launch_bounds__(256)
void pq_prep(const float* __restrict__ weight, const float* __restrict__ codebook,
             const float* __restrict__ x) {
    const int bid = blockIdx.x;
    const int tid = threadIdx.x;

    if (bid % QR != 0) {
        // ---- convert branch: one float4 of x per thread ----
        size_t conv_idx = (size_t)bid - bid / QR - 1;     // 0..32767
        size_t idx = conv_idx * 256 + tid;
        float4 v = ((const float4*)x)[idx];
        size_t m = idx >> 10;
        size_t kq = (idx & 1023) << 2;

        __nv_bfloat16 h0 = __float2bfloat16(v.x), h1 = __float2bfloat16(v.y);
        __nv_bfloat16 h2 = __float2bfloat16(v.z), h3 = __float2bfloat16(v.w);
        __nv_bfloat16 l0 = __float2bfloat16(v.x - __bfloat162float(h0));
        __nv_bfloat16 l1 = __float2bfloat16(v.y - __bfloat162float(h1));
        __nv_bfloat16 l2 = __float2bfloat16(v.z - __bfloat162float(h2));
        __nv_bfloat16 l3 = __float2bfloat16(v.w - __bfloat162float(h3));

        union { __nv_bfloat16 b[4]; uint2 u; } ph, pl;
        ph.b[0]=h0; ph.b[1]=h1; ph.b[2]=h2; ph.b[3]=h3;
        pl.b[0]=l0; pl.b[1]=l1; pl.b[2]=l2; pl.b[3]=l3;

        size_t base = m * K3 + kq;
        *(uint2*)(g_xcat + base)      = ph.u;   // x_hi
        *(uint2*)(g_xcat + base + K1) = pl.u;   // x_lo
        return;
    }

    // ---- quantize branch: one weight row ----
    __shared__ float cb[KCB * DGRP];
    __shared__ float cnorm_half[KCB];
    __shared__ float red[256];

    const int o = bid / QR;

    for (int i = tid; i < KCB * DGRP; i += 256) cb[i] = codebook[i];
    __syncthreads();
    {
        float s = 0.f;
        #pragma unroll
        for (int j = 0; j < DGRP; j++) { float c = cb[tid * DGRP + j]; s = fmaf(c, c, s); }
        cnorm_half[tid] = 0.5f * s;
    }
    const float* wrow = weight + (size_t)o * K1;
    float m = 0.f;
    for (int i = tid; i < K1; i += 256) m = fmaxf(m, fabsf(wrow[i]));
    red[tid] = m;
    __syncthreads();
    for (int s = 128; s > 0; s >>= 1) { if (tid < s) red[tid] = fmaxf(red[tid], red[tid + s]); __syncthreads(); }
    const float scale = fmaxf(red[0], 1e-6f);
    const float inv = 1.f / scale;

    const float4* wrow4 = (const float4*)wrow;
    float4 ga0 = wrow4[tid * 2],         ga1 = wrow4[tid * 2 + 1];
    float4 gb0 = wrow4[(tid + 256) * 2], gb1 = wrow4[(tid + 256) * 2 + 1];
    float gva[DGRP] = {ga0.x*inv, ga0.y*inv, ga0.z*inv, ga0.w*inv,
                       ga1.x*inv, ga1.y*inv, ga1.z*inv, ga1.w*inv};
    float gvb[DGRP] = {gb0.x*inv, gb0.y*inv, gb0.z*inv, gb0.w*inv,
                       gb1.x*inv, gb1.y*inv, gb1.z*inv, gb1.w*inv};

    float best0 = 3.4e38f, best1 = 3.4e38f;
    int bi0 = 0, bi1 = 0;
    const float4* cb4 = (const float4*)cb;
    #pragma unroll 2
    for (int k = 0; k < KCB; k++) {
        float4 c0 = cb4[k * 2], c1 = cb4[k * 2 + 1];
        float cn = cnorm_half[k];
        float d0 = cn, d1 = cn;
        d0 = fmaf(-gva[0], c0.x, d0); d1 = fmaf(-gvb[0], c0.x, d1);
        d0 = fmaf(-gva[1], c0.y, d0); d1 = fmaf(-gvb[1], c0.y, d1);
        d0 = fmaf(-gva[2], c0.z, d0); d1 = fmaf(-gvb[2], c0.z, d1);
        d0 = fmaf(-gva[3], c0.w, d0); d1 = fmaf(-gvb[3], c0.w, d1);
        d0 = fmaf(-gva[4], c1.x, d0); d1 = fmaf(-gvb[4], c1.x, d1);
        d0 = fmaf(-gva[5], c1.y, d0); d1 = fmaf(-gvb[5], c1.y, d1);
        d0 = fmaf(-gva[6], c1.z, d0); d1 = fmaf(-gvb[6], c1.z, d1);
        d0 = fmaf(-gva[7], c1.w, d0); d1 = fmaf(-gvb[7], c1.w, d1);
        if (d0 < best0) { best0 = d0; bi0 = k; }   // strict < keeps first min (matches argmin)
        if (d1 < best1) { best1 = d1; bi1 = k; }
    }

    __nv_bfloat16* wr = g_wcat + (size_t)o * K3;
    #pragma unroll
    for (int j = 0; j < DGRP; j++) {
        float w = cb[bi0 * DGRP + j] * scale;
        __nv_bfloat16 hi = __float2bfloat16(w);
        __nv_bfloat16 lo = __float2bfloat16(w - __bfloat162float(hi));
        int i = tid * DGRP + j;
        wr[i] = hi; wr[K1 + i] = lo;
    }
    #pragma unroll
    for (int j = 0; j < DGRP; j++) {
        float w = cb[bi1 * DGRP + j] * scale;
        __nv_bfloat16 hi = __float2bfloat16(w);
        __nv_bfloat16 lo = __float2bfloat16(w - __bfloat162float(hi));
        int i = (tid + 256) * DGRP + j;
        wr[i] = hi; wr[K1 + i] = lo;
    }
}

// ---------------- Kernel 2: bf16 HMMA GEMM, two-phase, 128x128, split-K=2 ----------------
// blockIdx.z selects K-half (2048 cols = 32 stages per phase).
// z=0 -> raw partial into out ; z=1 -> raw partial into g_part. Bias added in reduce.
__global__ __launch_bounds__(256, 2)
void pq_gemm_mma(float* __restrict__ out) {
    extern __shared__ char smem[];
    const uint32_t sbase = smem_u32(smem);
    const int tid  = threadIdx.x;
    const int wid  = tid >> 5;
    const int lane = tid & 31;

    const size_t m0 = (size_t)blockIdx.y * BM2;
    const size_t n0 = (size_t)blockIdx.x * BN2;
    const size_t gstride = (size_t)K3 * 2;        // row bytes
    const size_t kbase = (size_t)blockIdx.z * 4096;  // byte offset into each segment

    const char* ga[4]; const char* gb[4]; uint32_t chA[4], chB[4];
    #pragma unroll
    for (int i = 0; i < 4; i++) {
        int c = tid + 256 * i, row = c >> 3, ci = c & 7;
        uint32_t off = (uint32_t)(row * 128 + ((ci * 16) ^ ((row & 7) << 4)));
        ga[i] = (const char*)g_xcat + (m0 + row) * gstride + ci * 16 + kbase;
        gb[i] = (const char*)g_wcat + (n0 + row) * gstride + ci * 16 + kbase;
        chA[i] = off; chB[i] = off;
    }

    const int warp_m = (wid & 3) * 32;
    const int warp_n = (wid >> 2) * 64;
    const int rA  = warp_m + (lane & 7) + ((lane >> 3) & 1) * 8;
    const int ksA = ((lane >> 4) & 1) * 16;
    const int xmA = (rA & 7) << 4;
    const int rB  = warp_n + (lane & 7) + ((lane >> 4) & 1) * 8;
    const int ksB = ((lane >> 3) & 1) * 16;
    const int xmB = (rB & 7) << 4;

    float acc[2][8][4];
    #pragma unroll
    for (int i = 0; i < 2; i++)
        #pragma unroll
        for (int j = 0; j < 8; j++)
            #pragma unroll
            for (int q = 0; q < 4; q++) acc[i][j][q] = 0.f;

    // ================= Phase A: 2-stage ring, 48KB stages, 1 barrier/stage =================
    {
        uint32_t bofs = sbase;
        #pragma unroll
        for (int i = 0; i < 4; i++) {
            CP_ASYNC16(bofs + chA[i],            ga[i]);           // xh
            CP_ASYNC16(bofs + A_TILE + chA[i],   ga[i] + 8192);    // xl
            CP_ASYNC16(bofs + 2*A_TILE + chB[i], gb[i]);           // wh
        }
        CP_COMMIT();
    }

    for (int s = 0; s < NSTG; s++) {
        CP_WAIT0();        // stage s fully landed (only group in flight)
        __syncthreads();   // all warps finished compute(s-1) + see buf s

        if (s + 1 < NSTG) {
            uint32_t bofs = sbase + ((s + 1) & 1) * PH_A_STAGE;
            size_t ko = (size_t)(s + 1) * 128;
            #pragma unroll
            for (int i = 0; i < 4; i++) {
                CP_ASYNC16(bofs + chA[i],            ga[i] + ko);
                CP_ASYNC16(bofs + A_TILE + chA[i],   ga[i] + ko + 8192);
                CP_ASYNC16(bofs + 2*A_TILE + chB[i], gb[i] + ko);
            }
        }
        CP_COMMIT();

        const uint32_t sXH = sbase + (s & 1) * PH_A_STAGE;
        const uint32_t sXL = sXH + A_TILE;
        const uint32_t sWH = sXH + 2 * A_TILE;

        #pragma unroll
        for (int ks = 0; ks < 4; ks++) {
            uint32_t ah[2][4], al[2][4];
            #pragma unroll
            for (int i = 0; i < 2; i++) {
                uint32_t aoff = (rA + i * 16) * 128 + ((ks * 32 + ksA) ^ xmA);
                LDSM_X4(ah[i][0], ah[i][1], ah[i][2], ah[i][3], sXH + aoff);
                LDSM_X4(al[i][0], al[i][1], al[i][2], al[i][3], sXL + aoff);
            }
            uint32_t b[4][4];
            #pragma unroll
            for (int blk = 0; blk < 4; blk++) {
                uint32_t boff = (rB + blk * 16) * 128 + ((ks * 32 + ksB) ^ xmB);
                LDSM_X4(b[blk][0], b[blk][1], b[blk][2], b[blk][3], sWH + boff);
            }
            #pragma unroll
            for (int i = 0; i < 2; i++)
                #pragma unroll
                for (int jj = 0; jj < 8; jj++) {
                    int blk = jj >> 1, hb = (jj & 1) * 2;
                    MMA16816(acc[i][jj], ah[i][0], ah[i][1], ah[i][2], ah[i][3],
                             b[blk][hb], b[blk][hb + 1]);
                    MMA16816(acc[i][jj], al[i][0], al[i][1], al[i][2], al[i][3],
                             b[blk][hb], b[blk][hb + 1]);
                }
        }
    }

    // ================= Phase transition =================
    CP_WAIT0();
    __syncthreads();
    #pragma unroll
    for (int s = 0; s < 2; s++) {
        uint32_t bofs = sbase + s * PH_B_STAGE;
        size_t ko = (size_t)s * 128;
        #pragma unroll
        for (int i = 0; i < 4; i++) {
            CP_ASYNC16(bofs + chA[i],          ga[i] + ko);          // xh
            CP_ASYNC16(bofs + A_TILE + chB[i], gb[i] + ko + 8192);   // wl
        }
        CP_COMMIT();
    }

    // ================= Phase B: 3-stage ring, 1 barrier/stage =================
    for (int s = 0; s < NSTG; s++) {
        CP_WAIT1();
        __syncthreads();   // separates compute(s-1) from prefetch (s+2)%3 == (s-1)%3

        if (s + 2 < NSTG) {
            uint32_t bofs = sbase + ((s + 2) % 3) * PH_B_STAGE;
            size_t ko = (size_t)(s + 2) * 128;
            #pragma unroll
            for (int i = 0; i < 4; i++) {
                CP_ASYNC16(bofs + chA[i],          ga[i] + ko);
                CP_ASYNC16(bofs + A_TILE + chB[i], gb[i] + ko + 8192);
            }
        }
        CP_COMMIT();

        const uint32_t sA = sbase + (s % 3) * PH_B_STAGE;
        const uint32_t sB = sA + A_TILE;

        #pragma unroll
        for (int ks = 0; ks < 4; ks++) {
            uint32_t a[2][4];
            #pragma unroll
            for (int i = 0; i < 2; i++) {
                uint32_t aoff = (rA + i * 16) * 128 + ((ks * 32 + ksA) ^ xmA);
                LDSM_X4(a[i][0], a[i][1], a[i][2], a[i][3], sA + aoff);
            }
            uint32_t b[4][4];
            #pragma unroll
            for (int blk = 0; blk < 4; blk++) {
                uint32_t boff = (rB + blk * 16) * 128 + ((ks * 32 + ksB) ^ xmB);
                LDSM_X4(b[blk][0], b[blk][1], b[blk][2], b[blk][3], sB + boff);
            }
            #pragma unroll
            for (int i = 0; i < 2; i++)
                #pragma unroll
                for (int jj = 0; jj < 8; jj++) {
                    int blk = jj >> 1, hb = (jj & 1) * 2;
                    MMA16816(acc[i][jj], a[i][0], a[i][1], a[i][2], a[i][3],
                             b[blk][hb], b[blk][hb + 1]);
                }
        }
    }

    // epilogue: raw partial stores (no bias; reduce adds it once)
    float* dst = blockIdx.z ? g_part : out;
    const int mrow = (int)m0 + warp_m + (lane >> 2);
    const int ncol = (int)n0 + warp_n + (lane & 3) * 2;
    #pragma unroll
    for (int i = 0; i < 2; i++) {
        #pragma unroll
        for (int jj = 0; jj < 8; jj++) {
            int col = ncol + jj * 8;
            int r0 = mrow + i * 16, r1 = r0 + 8;
            float2 v0, v1;
            v0.x = acc[i][jj][0]; v0.y = acc[i][jj][1];
            v1.x = acc[i][jj][2]; v1.y = acc[i][jj][3];
            *(float2*)(dst + (size_t)r0 * N_DIM + col) = v0;
            *(float2*)(dst + (size_t)r1 * N_DIM + col) = v1;
        }
    }
}

// ---------------- Kernel 3: out = out + g_part + bias ----------------
__global__ __launch_bounds__(256)
void pq_reduce(float* __restrict__ out, const float* __restrict__ bias) {
    size_t idx = (size_t)blockIdx.x * 256 + threadIdx.x;   // one float4
    float4 a = ((const float4*)out)[idx];
    float4 b = ((const float4*)g_part)[idx];
    float4 bv = ((const float4*)bias)[idx & 511];           // (idx*4) % 2048 / 4
    float4 r;
    r.x = a.x + b.x + bv.x;
    r.y = a.y + b.y + bv.y;
    r.z = a.z + b.z + bv.z;
    r.w = a.w + b.w + bv.w;
    ((float4*)out)[idx] = r;
}

// ---------------- launch ----------------
extern "C" void kernel_launch(void* const* d_in, const int* in_sizes, int n_in,
                              void* d_out, int out_size) {
    const float* x        = (const float*)d_in[0];
    const float* weight   = (const float*)d_in[1];
    const float* codebook = (const float*)d_in[2];
    const float* bias     = (const float*)d_in[3];
    float* out = (float*)d_out;

    pq_prep<<<PREP_GRID, 256>>>(weight, codebook, x);

    cudaFuncSetAttribute(pq_gemm_mma, cudaFuncAttributeMaxDynamicSharedMemorySize, SMEM_G);
    dim3 grid(N_DIM / BN2, M_DIM / BM2, 2);   // (16, 64, 2) = 2048 CTAs
    pq_gemm_mma<<<grid, 256, SMEM_G>>>(out);

    pq_reduce<<<(M_DIM * N_DIM / 4) / 256, 256>>>(out, bias);
}

// round 16
// speedup vs baseline: 1.8154x; 1.5826x over previous
#include <cuda_runtime.h>
#include <cuda_bf16.h>
#include <cstdint>

#define K1    4096
#define K3    8192           // stored K: [hi | lo] segments
#define N_DIM 2048
#define M_DIM 8192
#define DGRP  8
#define KCB   256

// GEMM: 128x128 CTA, 256 threads (8 warps, 4x2 grid of 32x64 warp tiles)
#define BM2    128
#define BN2    128
#define A_TILE 16384                       // 128 rows x 128B
#define PH_A_STAGE (3 * A_TILE)            // xh + xl + wh = 49152
#define PH_B_STAGE (2 * A_TILE)            // xh + wl      = 32768
#define SMEM_G 98304                       // 2 x phaseA == 3 x phaseB ; 2 CTAs/SM

// fused prep grid: 2048 quantize rows + 32768 convert chunks, interleaved 1:16
#define QR 17
#define PREP_GRID (2048 + 32768)

__device__ __align__(256) __nv_bfloat16 g_xcat[(size_t)M_DIM * K3];  // [xhi|xlo]
__device__ __align__(256) __nv_bfloat16 g_wcat[(size_t)N_DIM * K3];  // [whi|wlo]

// ---------------- PTX helpers ----------------
__device__ __forceinline__ uint32_t smem_u32(const void* p) {
    uint32_t a;
    asm("{ .reg .u64 t; cvta.to.shared.u64 t, %1; cvt.u32.u64 %0, t; }" : "=r"(a) : "l"(p));
    return a;
}
#define CP_ASYNC16(dst, src) \
    asm volatile("cp.async.cg.shared.global [%0], [%1], 16;" :: "r"(dst), "l"(src))
#define CP_COMMIT() asm volatile("cp.async.commit_group;" ::: "memory")
#define CP_WAIT1()  asm volatile("cp.async.wait_group 1;" ::: "memory")
#define CP_WAIT0()  asm volatile("cp.async.wait_group 0;" ::: "memory")

#define LDSM_X4(r0,r1,r2,r3,addr) \
    asm volatile("ldmatrix.sync.aligned.m8n8.x4.shared.b16 {%0,%1,%2,%3}, [%4];" \
                 : "=r"(r0), "=r"(r1), "=r"(r2), "=r"(r3) : "r"(addr))

#define MMA16816(d, a0,a1,a2,a3, b0,b1) \
    asm volatile("mma.sync.aligned.m16n8k16.row.col.f32.bf16.bf16.f32 " \
                 "{%0,%1,%2,%3},{%4,%5,%6,%7},{%8,%9},{%0,%1,%2,%3};" \
                 : "+f"((d)[0]), "+f"((d)[1]), "+f"((d)[2]), "+f"((d)[3]) \
                 : "r"(a0), "r"(a1), "r"(a2), "r"(a3), "r"(b0), "r"(b1))

// ---------------- Kernel 1 (fused): quantize rows || x bf16 hi/lo convert ----------------
__global__ __launch_bounds__(256)
void pq_prep(const float* __restrict__ weight, const float* __restrict__ codebook,
             const float* __restrict__ x) {
    const int bid = blockIdx.x;
    const int tid = threadIdx.x;

    if (bid % QR != 0) {
        // ---- convert branch: one float4 of x per thread ----
        size_t conv_idx = (size_t)bid - bid / QR - 1;     // 0..32767
        size_t idx = conv_idx * 256 + tid;
        float4 v = ((const float4*)x)[idx];
        size_t m = idx >> 10;
        size_t kq = (idx & 1023) << 2;

        __nv_bfloat16 h0 = __float2bfloat16(v.x), h1 = __float2bfloat16(v.y);
        __nv_bfloat16 h2 = __float2bfloat16(v.z), h3 = __float2bfloat16(v.w);
        __nv_bfloat16 l0 = __float2bfloat16(v.x - __bfloat162float(h0));
        __nv_bfloat16 l1 = __float2bfloat16(v.y - __bfloat162float(h1));
        __nv_bfloat16 l2 = __float2bfloat16(v.z - __bfloat162float(h2));
        __nv_bfloat16 l3 = __float2bfloat16(v.w - __bfloat162float(h3));

        union { __nv_bfloat16 b[4]; uint2 u; } ph, pl;
        ph.b[0]=h0; ph.b[1]=h1; ph.b[2]=h2; ph.b[3]=h3;
        pl.b[0]=l0; pl.b[1]=l1; pl.b[2]=l2; pl.b[3]=l3;

        size_t base = m * K3 + kq;
        *(uint2*)(g_xcat + base)      = ph.u;   // x_hi
        *(uint2*)(g_xcat + base + K1) = pl.u;   // x_lo
        return;
    }

    // ---- quantize branch: one weight row ----
    __shared__ float cb[KCB * DGRP];
    __shared__ float cnorm_half[KCB];
    __shared__ float red[256];

    const int o = bid / QR;

    for (int i = tid; i < KCB * DGRP; i += 256) cb[i] = codebook[i];
    __syncthreads();
    {
        float s = 0.f;
        #pragma unroll
        for (int j = 0; j < DGRP; j++) { float c = cb[tid * DGRP + j]; s = fmaf(c, c, s); }
        cnorm_half[tid] = 0.5f * s;
    }
    const float* wrow = weight + (size_t)o * K1;
    float m = 0.f;
    for (int i = tid; i < K1; i += 256) m = fmaxf(m, fabsf(wrow[i]));
    red[tid] = m;
    __syncthreads();
    for (int s = 128; s > 0; s >>= 1) { if (tid < s) red[tid] = fmaxf(red[tid], red[tid + s]); __syncthreads(); }
    const float scale = fmaxf(red[0], 1e-6f);
    const float inv = 1.f / scale;

    const float4* wrow4 = (const float4*)wrow;
    float4 ga0 = wrow4[tid * 2],         ga1 = wrow4[tid * 2 + 1];
    float4 gb0 = wrow4[(tid + 256) * 2], gb1 = wrow4[(tid + 256) * 2 + 1];
    float gva[DGRP] = {ga0.x*inv, ga0.y*inv, ga0.z*inv, ga0.w*inv,
                       ga1.x*inv, ga1.y*inv, ga1.z*inv, ga1.w*inv};
    float gvb[DGRP] = {gb0.x*inv, gb0.y*inv, gb0.z*inv, gb0.w*inv,
                       gb1.x*inv, gb1.y*inv, gb1.z*inv, gb1.w*inv};

    float best0 = 3.4e38f, best1 = 3.4e38f;
    int bi0 = 0, bi1 = 0;
    const float4* cb4 = (const float4*)cb;
    #pragma unroll 2
    for (int k = 0; k < KCB; k++) {
        float4 c0 = cb4[k * 2], c1 = cb4[k * 2 + 1];
        float cn = cnorm_half[k];
        float d0 = cn, d1 = cn;
        d0 = fmaf(-gva[0], c0.x, d0); d1 = fmaf(-gvb[0], c0.x, d1);
        d0 = fmaf(-gva[1], c0.y, d0); d1 = fmaf(-gvb[1], c0.y, d1);
        d0 = fmaf(-gva[2], c0.z, d0); d1 = fmaf(-gvb[2], c0.z, d1);
        d0 = fmaf(-gva[3], c0.w, d0); d1 = fmaf(-gvb[3], c0.w, d1);
        d0 = fmaf(-gva[4], c1.x, d0); d1 = fmaf(-gvb[4], c1.x, d1);
        d0 = fmaf(-gva[5], c1.y, d0); d1 = fmaf(-gvb[5], c1.y, d1);
        d0 = fmaf(-gva[6], c1.z, d0); d1 = fmaf(-gvb[6], c1.z, d1);
        d0 = fmaf(-gva[7], c1.w, d0); d1 = fmaf(-gvb[7], c1.w, d1);
        if (d0 < best0) { best0 = d0; bi0 = k; }   // strict < keeps first min (matches argmin)
        if (d1 < best1) { best1 = d1; bi1 = k; }
    }

    __nv_bfloat16* wr = g_wcat + (size_t)o * K3;
    #pragma unroll
    for (int j = 0; j < DGRP; j++) {
        float w = cb[bi0 * DGRP + j] * scale;
        __nv_bfloat16 hi = __float2bfloat16(w);
        __nv_bfloat16 lo = __float2bfloat16(w - __bfloat162float(hi));
        int i = tid * DGRP + j;
        wr[i] = hi; wr[K1 + i] = lo;
    }
    #pragma unroll
    for (int j = 0; j < DGRP; j++) {
        float w = cb[bi1 * DGRP + j] * scale;
        __nv_bfloat16 hi = __float2bfloat16(w);
        __nv_bfloat16 lo = __float2bfloat16(w - __bfloat162float(hi));
        int i = (tid + 256) * DGRP + j;
        wr[i] = hi; wr[K1 + i] = lo;
    }
}

// ---------------- Kernel 2: bf16 HMMA GEMM, two-phase, 128x128 (round-13 structure) ----------------
// Phase A (64 stages): stage = {xh, xl, wh}; acc += xh*wh + xl*wh (wh regs reused)
//   single barrier per stage: wait(0) -> sync -> prefetch(s+1) -> compute(s)
// Phase B (64 stages): stage = {xh, wl};     acc += xh*wl  (3-stage ring, wait(1))
__global__ __launch_bounds__(256, 2)
void pq_gemm_mma(const float* __restrict__ bias, float* __restrict__ out) {
    extern __shared__ char smem[];
    const uint32_t sbase = smem_u32(smem);
    const int tid  = threadIdx.x;
    const int wid  = tid >> 5;
    const int lane = tid & 31;

    const size_t m0 = (size_t)blockIdx.y * BM2;
    const size_t n0 = (size_t)blockIdx.x * BN2;
    const size_t gstride = (size_t)K3 * 2;   // row bytes

    const char* ga[4]; const char* gb[4]; uint32_t chA[4], chB[4];
    #pragma unroll
    for (int i = 0; i < 4; i++) {
        int c = tid + 256 * i, row = c >> 3, ci = c & 7;
        uint32_t off = (uint32_t)(row * 128 + ((ci * 16) ^ ((row & 7) << 4)));
        ga[i] = (const char*)g_xcat + (m0 + row) * gstride + ci * 16;
        gb[i] = (const char*)g_wcat + (n0 + row) * gstride + ci * 16;
        chA[i] = off; chB[i] = off;
    }

    const int warp_m = (wid & 3) * 32;
    const int warp_n = (wid >> 2) * 64;
    const int rA  = warp_m + (lane & 7) + ((lane >> 3) & 1) * 8;
    const int ksA = ((lane >> 4) & 1) * 16;
    const int xmA = (rA & 7) << 4;
    const int rB  = warp_n + (lane & 7) + ((lane >> 4) & 1) * 8;
    const int ksB = ((lane >> 3) & 1) * 16;
    const int xmB = (rB & 7) << 4;

    float acc[2][8][4];
    #pragma unroll
    for (int i = 0; i < 2; i++)
        #pragma unroll
        for (int j = 0; j < 8; j++)
            #pragma unroll
            for (int q = 0; q < 4; q++) acc[i][j][q] = 0.f;

    // ================= Phase A: 2-stage ring, 48KB stages, 1 barrier/stage =================
    {
        uint32_t bofs = sbase;
        #pragma unroll
        for (int i = 0; i < 4; i++) {
            CP_ASYNC16(bofs + chA[i],            ga[i]);           // xh
            CP_ASYNC16(bofs + A_TILE + chA[i],   ga[i] + 8192);    // xl
            CP_ASYNC16(bofs + 2*A_TILE + chB[i], gb[i]);           // wh
        }
        CP_COMMIT();
    }

    for (int s = 0; s < 64; s++) {
        CP_WAIT0();        // stage s fully landed (only group in flight)
        __syncthreads();   // all warps finished compute(s-1) [buf (s-1)&1 == (s+1)&1] + see buf s

        if (s + 1 < 64) {
            uint32_t bofs = sbase + ((s + 1) & 1) * PH_A_STAGE;
            size_t ko = (size_t)(s + 1) * 128;
            #pragma unroll
            for (int i = 0; i < 4; i++) {
                CP_ASYNC16(bofs + chA[i],            ga[i] + ko);
                CP_ASYNC16(bofs + A_TILE + chA[i],   ga[i] + ko + 8192);
                CP_ASYNC16(bofs + 2*A_TILE + chB[i], gb[i] + ko);
            }
        }
        CP_COMMIT();

        const uint32_t sXH = sbase + (s & 1) * PH_A_STAGE;
        const uint32_t sXL = sXH + A_TILE;
        const uint32_t sWH = sXH + 2 * A_TILE;

        #pragma unroll
        for (int ks = 0; ks < 4; ks++) {
            uint32_t ah[2][4], al[2][4];
            #pragma unroll
            for (int i = 0; i < 2; i++) {
                uint32_t aoff = (rA + i * 16) * 128 + ((ks * 32 + ksA) ^ xmA);
                LDSM_X4(ah[i][0], ah[i][1], ah[i][2], ah[i][3], sXH + aoff);
                LDSM_X4(al[i][0], al[i][1], al[i][2], al[i][3], sXL + aoff);
            }
            uint32_t b[4][4];
            #pragma unroll
            for (int blk = 0; blk < 4; blk++) {
                uint32_t boff = (rB + blk * 16) * 128 + ((ks * 32 + ksB) ^ xmB);
                LDSM_X4(b[blk][0], b[blk][1], b[blk][2], b[blk][3], sWH + boff);
            }
            #pragma unroll
            for (int i = 0; i < 2; i++)
                #pragma unroll
                for (int jj = 0; jj < 8; jj++) {
                    int blk = jj >> 1, hb = (jj & 1) * 2;
                    MMA16816(acc[i][jj], ah[i][0], ah[i][1], ah[i][2], ah[i][3],
                             b[blk][hb], b[blk][hb + 1]);
                    MMA16816(acc[i][jj], al[i][0], al[i][1], al[i][2], al[i][3],
                             b[blk][hb], b[blk][hb + 1]);
                }
        }
    }

    // ================= Phase transition =================
    CP_WAIT0();
    __syncthreads();
    #pragma unroll
    for (int s = 0; s < 2; s++) {
        uint32_t bofs = sbase + s * PH_B_STAGE;
        size_t ko = (size_t)s * 128;
        #pragma unroll
        for (int i = 0; i < 4; i++) {
            CP_ASYNC16(bofs + chA[i],          ga[i] + ko);          // xh
            CP_ASYNC16(bofs + A_TILE + chB[i], gb[i] + ko + 8192);   // wl
        }
        CP_COMMIT();
    }

    // ================= Phase B: 3-stage ring, 1 barrier/stage =================
    for (int s = 0; s < 64; s++) {
        CP_WAIT1();
        __syncthreads();   // separates compute(s-1) from prefetch (s+2)%3 == (s-1)%3

        if (s + 2 < 64) {
            uint32_t bofs = sbase + ((s + 2) % 3) * PH_B_STAGE;
            size_t ko = (size_t)(s + 2) * 128;
            #pragma unroll
            for (int i = 0; i < 4; i++) {
                CP_ASYNC16(bofs + chA[i],          ga[i] + ko);
                CP_ASYNC16(bofs + A_TILE + chB[i], gb[i] + ko + 8192);
            }
        }
        CP_COMMIT();

        const uint32_t sA = sbase + (s % 3) * PH_B_STAGE;
        const uint32_t sB = sA + A_TILE;

        #pragma unroll
        for (int ks = 0; ks < 4; ks++) {
            uint32_t a[2][4];
            #pragma unroll
            for (int i = 0; i < 2; i++) {
                uint32_t aoff = (rA + i * 16) * 128 + ((ks * 32 + ksA) ^ xmA);
                LDSM_X4(a[i][0], a[i][1], a[i][2], a[i][3], sA + aoff);
            }
            uint32_t b[4][4];
            #pragma unroll
            for (int blk = 0; blk < 4; blk++) {
                uint32_t boff = (rB + blk * 16) * 128 + ((ks * 32 + ksB) ^ xmB);
                LDSM_X4(b[blk][0], b[blk][1], b[blk][2], b[blk][3], sB + boff);
            }
            #pragma unroll
            for (int i = 0; i < 2; i++)
                #pragma unroll
                for (int jj = 0; jj < 8; jj++) {
                    int blk = jj >> 1, hb = (jj & 1) * 2;
                    MMA16816(acc[i][jj], a[i][0], a[i][1], a[i][2], a[i][3],
                             b[blk][hb], b[blk][hb + 1]);
                }
        }
    }

    // epilogue: direct stores + bias
    const int mrow = (int)m0 + warp_m + (lane >> 2);
    const int ncol = (int)n0 + warp_n + (lane & 3) * 2;
    #pragma unroll
    for (int i = 0; i < 2; i++) {
        #pragma unroll
        for (int jj = 0; jj < 8; jj++) {
            int col = ncol + jj * 8;
            float2 bv = *(const float2*)&bias[col];
            int r0 = mrow + i * 16, r1 = r0 + 8;
            float2 v0, v1;
            v0.x = acc[i][jj][0] + bv.x; v0.y = acc[i][jj][1] + bv.y;
            v1.x = acc[i][jj][2] + bv.x; v1.y = acc[i][jj][3] + bv.y;
            *(float2*)(out + (size_t)r0 * N_DIM + col) = v0;
            *(float2*)(out + (size_t)r1 * N_DIM + col) = v1;
        }
    }
}

// ---------------- launch ----------------
extern "C" void kernel_launch(void* const* d_in, const int* in_sizes, int n_in,
                              void* d_out, int out_size) {
    const float* x        = (const float*)d_in[0];
    const float* weight   = (const float*)d_in[1];
    const float* codebook = (const float*)d_in[2];
    const float* bias     = (const float*)d_in[3];
    float* out = (float*)d_out;

    pq_prep<<<PREP_GRID, 256>>>(weight, codebook, x);

    cudaFuncSetAttribute(pq_gemm_mma, cudaFuncAttributeMaxDynamicSharedMemorySize, SMEM_G);
    dim3 grid(N_DIM / BN2, M_DIM / BM2);   // (16, 64) = 1024 CTAs
    pq_gemm_mma<<<grid, 256, SMEM_G>>>(bias, out);
}